// round 3
// baseline (speedup 1.0000x reference)
#include <cuda_runtime.h>
#include <math.h>
#include <stdint.h>

#define NN 40000
#define NE 640000
#define FIN 64
#define FE 16
#define NG 1000
#define HD 256
#define OD 128
#define K1 144            // FIN + FIN + FE
#define MT (NE + NN)      // edges + self loops = 680000

// ---------------- scratch (device globals; no runtime allocation) ----------
__device__ __align__(16) int   d_src[NE];
__device__ __align__(16) int   d_dst[NE];
__device__ __align__(16) int   d_bat[NN];
__device__            int      d_flag64;
__device__ __align__(16) float d_xagg[NN * FIN];
__device__ __align__(16) float d_easum[NN * FE];
__device__ __align__(16) float d_deg[NN];
__device__ __align__(16) float d_xin[(size_t)NN * K1];
__device__ __align__(16) float d_Wcat[K1 * HD];
__device__ __align__(16) float d_h[(size_t)NN * HD];
__device__ __align__(16) float d_Wlr[HD * 2 * OD];
__device__ __align__(16) float d_blr[2 * OD];
__device__ __align__(16) float d_xlr[(size_t)NN * 2 * OD];
__device__ __align__(16) float d_alpha[MT];
__device__ __align__(16) unsigned d_amax[NN];
__device__ __align__(16) float d_denom[NN];
__device__ __align__(16) float d_outn[(size_t)NN * OD];
__device__ __align__(16) float d_gsum[NG * OD];
__device__ __align__(16) float d_gcnt[NG];

// ---------------- helpers ----------------
__device__ __forceinline__ float gelu_t(float x) {
    float u = 0.7978845608028654f * (x + 0.044715f * x * x * x);
    return 0.5f * x * (1.0f + tanhf(u));
}

__device__ __forceinline__ void atomicMaxF(unsigned* addr, float v) {
    if (v >= 0.0f) atomicMax((int*)addr, __float_as_int(v));
    else           atomicMin(addr, __float_as_uint(v));
}

// ---------------- index dtype sniff + normalize ----------------
__global__ void k_detect(const int* __restrict__ ei) {
    // int64 (little-endian, values < 2^31): every odd int32 word is 0.
    int allz = 1;
    for (int i = 1; i < 64; i += 2) if (ei[i] != 0) allz = 0;
    d_flag64 = allz;
}

__global__ void k_convert(const int* __restrict__ ei, const int* __restrict__ bat) {
    int i = blockIdx.x * blockDim.x + threadIdx.x;
    int f = d_flag64;
    if (i < NE) {
        if (f) { d_src[i] = ei[2 * i]; d_dst[i] = ei[2 * (NE + i)]; }
        else   { d_src[i] = ei[i];     d_dst[i] = ei[NE + i]; }
    }
    if (i < NN) d_bat[i] = f ? bat[2 * i] : bat[i];
}

// ---------------- layer-1 edge scatter (x and edge_attr, by dst) ----------
__global__ void k_scatter(const float* __restrict__ x, const float* __restrict__ ea) {
    int w = (blockIdx.x * blockDim.x + threadIdx.x) >> 5;
    if (w >= NE) return;
    int lane = threadIdx.x & 31;
    int s = d_src[w], d = d_dst[w];
    if (lane < 16) {
        float4 v = __ldg((const float4*)(x + (size_t)s * FIN) + lane);
        atomicAdd((float4*)(d_xagg + (size_t)d * FIN) + lane, v);
    } else if (lane < 20) {
        float4 v = __ldg((const float4*)(ea + (size_t)w * FE) + (lane - 16));
        atomicAdd((float4*)(d_easum + (size_t)d * FE) + (lane - 16), v);
    } else if (lane == 20) {
        atomicAdd(&d_deg[d], 1.0f);
    }
}

// ---------------- pack fused weights ----------------
__global__ void k_packw(const float* __restrict__ Wmsg, const float* __restrict__ Wself,
                        const float* __restrict__ We1, const float* __restrict__ Wl,
                        const float* __restrict__ bl, const float* __restrict__ Wr,
                        const float* __restrict__ br) {
    int i = blockIdx.x * blockDim.x + threadIdx.x;
    if (i < 64 * HD)       d_Wcat[i] = Wmsg[i];
    else if (i < 128 * HD) d_Wcat[i] = Wself[i - 64 * HD];
    else if (i < K1 * HD)  d_Wcat[i] = We1[i - 128 * HD];
    if (i < HD * 2 * OD) {
        int k = i >> 8, c = i & 255;
        d_Wlr[i] = (c < OD) ? Wl[k * OD + c] : Wr[k * OD + (c - OD)];
    }
    if (i < 2 * OD) d_blr[i] = (i < OD) ? bl[i] : br[i - OD];
}

// ---------------- pack xin = [xagg | x | easum] ----------------
__global__ void k_packxin(const float* __restrict__ x) {
    int i = blockIdx.x * blockDim.x + threadIdx.x;
    if (i >= NN * K1) return;
    int v = i / K1, c = i - v * K1;
    float val;
    if (c < 64)       val = d_xagg[v * 64 + c];
    else if (c < 128) val = x[(size_t)v * 64 + (c - 64)];
    else              val = d_easum[v * 16 + (c - 128)];
    d_xin[i] = val;
}

// ---------------- fp32 SGEMM, 64x64 tile, 256 threads, 4x4 micro ----------
// MODE 0: h = gelu(xin@Wcat + deg*(b_msg+b_edge1) + b_self)   (K = 144)
// MODE 1: xlr = h@Wlr + blr                                   (K = 256)
template <int MODE, int K>
__global__ void __launch_bounds__(256, 4)
k_gemm(const float* __restrict__ bm, const float* __restrict__ be1,
       const float* __restrict__ bs) {
    __shared__ float As[16][68];
    __shared__ float Bs[16][64];
    const float* A = (MODE == 0) ? d_xin : d_h;
    const float* B = (MODE == 0) ? d_Wcat : d_Wlr;
    float* C       = (MODE == 0) ? d_h : d_xlr;

    int r0 = blockIdx.x * 64, c0 = blockIdx.y * 64;
    int t = threadIdx.x;
    int tx = t & 15, ty = t >> 4;
    float acc[4][4];
#pragma unroll
    for (int i = 0; i < 4; i++)
#pragma unroll
        for (int j = 0; j < 4; j++) acc[i][j] = 0.0f;

    int lr = t >> 2;          // A load row 0..63
    int lk = (t & 3) * 4;     // A load k offset
    int lkb = t >> 4;         // B load k 0..15
    int lcb = (t & 15) * 4;   // B load col

    for (int kt = 0; kt < K; kt += 16) {
        float4 a4 = *(const float4*)(A + (size_t)(r0 + lr) * K + kt + lk);
        As[lk + 0][lr] = a4.x; As[lk + 1][lr] = a4.y;
        As[lk + 2][lr] = a4.z; As[lk + 3][lr] = a4.w;
        *(float4*)(&Bs[lkb][lcb]) =
            *(const float4*)(B + (size_t)(kt + lkb) * 256 + c0 + lcb);
        __syncthreads();
#pragma unroll
        for (int kk = 0; kk < 16; kk++) {
            float4 av = *(const float4*)(&As[kk][ty * 4]);
            float4 bv = *(const float4*)(&Bs[kk][tx * 4]);
            float ar[4] = {av.x, av.y, av.z, av.w};
            float br2[4] = {bv.x, bv.y, bv.z, bv.w};
#pragma unroll
            for (int i = 0; i < 4; i++)
#pragma unroll
                for (int j = 0; j < 4; j++)
                    acc[i][j] = fmaf(ar[i], br2[j], acc[i][j]);
        }
        __syncthreads();
    }

#pragma unroll
    for (int i = 0; i < 4; i++) {
        int row = r0 + ty * 4 + i;
        float dg = (MODE == 0) ? d_deg[row] : 0.0f;
#pragma unroll
        for (int j = 0; j < 4; j++) {
            int col = c0 + tx * 4 + j;
            float v = acc[i][j];
            if (MODE == 0) {
                v += dg * (bm[col] + be1[col]) + bs[col];
                v = gelu_t(v);
            } else {
                v += d_blr[col];
            }
            C[(size_t)row * 256 + col] = v;
        }
    }
}

// ---------------- GATv2 pass 1: alpha + segment max (warp per edge) -------
__global__ void k_att1(const float* __restrict__ ea, const float* __restrict__ We2,
                       const float* __restrict__ att) {
    __shared__ float sW[FE * OD];
    __shared__ float sA[OD];
    for (int i = threadIdx.x; i < FE * OD; i += blockDim.x) sW[i] = We2[i];
    for (int i = threadIdx.x; i < OD; i += blockDim.x) sA[i] = att[i];
    __syncthreads();

    int w = (blockIdx.x * blockDim.x + threadIdx.x) >> 5;
    if (w >= MT) return;
    int lane = threadIdx.x & 31;

    int s, d;
    float ear[FE];
    if (w < NE) {
        s = d_src[w]; d = d_dst[w];
        const float4* p4 = (const float4*)(ea + (size_t)w * FE);
#pragma unroll
        for (int q = 0; q < 4; q++) {
            float4 e = __ldg(p4 + q);
            ear[q * 4 + 0] = e.x; ear[q * 4 + 1] = e.y;
            ear[q * 4 + 2] = e.z; ear[q * 4 + 3] = e.w;
        }
    } else {
        int v = w - NE; s = v; d = v;
        float inv = 1.0f / fmaxf(d_deg[v], 1.0f);
        const float4* p4 = (const float4*)(d_easum + (size_t)v * FE);
#pragma unroll
        for (int q = 0; q < 4; q++) {
            float4 e = p4[q];
            ear[q * 4 + 0] = e.x * inv; ear[q * 4 + 1] = e.y * inv;
            ear[q * 4 + 2] = e.z * inv; ear[q * 4 + 3] = e.w * inv;
        }
    }

    int k0 = lane * 4;
    float4 vl = *(const float4*)(d_xlr + (size_t)s * 256 + k0);
    float4 vr = *(const float4*)(d_xlr + (size_t)d * 256 + 128 + k0);
    float m0 = vl.x + vr.x, m1 = vl.y + vr.y, m2 = vl.z + vr.z, m3 = vl.w + vr.w;
#pragma unroll
    for (int i = 0; i < FE; i++) {
        float e = ear[i];
        float4 wv = *(const float4*)(&sW[i * OD + k0]);
        m0 = fmaf(e, wv.x, m0); m1 = fmaf(e, wv.y, m1);
        m2 = fmaf(e, wv.z, m2); m3 = fmaf(e, wv.w, m3);
    }
    m0 = m0 > 0.f ? m0 : 0.2f * m0;
    m1 = m1 > 0.f ? m1 : 0.2f * m1;
    m2 = m2 > 0.f ? m2 : 0.2f * m2;
    m3 = m3 > 0.f ? m3 : 0.2f * m3;
    float4 a4 = *(const float4*)(&sA[k0]);
    float a = m0 * a4.x + m1 * a4.y + m2 * a4.z + m3 * a4.w;
#pragma unroll
    for (int o = 16; o; o >>= 1) a += __shfl_xor_sync(0xFFFFFFFFu, a, o);
    if (lane == 0) {
        d_alpha[w] = a;
        atomicMaxF(&d_amax[d], a);
    }
}

// ---------------- GATv2 pass 2: exp + denom ----------------
__global__ void k_att2() {
    int m = blockIdx.x * blockDim.x + threadIdx.x;
    if (m >= MT) return;
    int d = (m < NE) ? d_dst[m] : (m - NE);
    float amax = __uint_as_float(d_amax[d]);
    float wv = expf(d_alpha[m] - amax);
    d_alpha[m] = wv;
    atomicAdd(&d_denom[d], wv);
}

// ---------------- GATv2 pass 3: weighted scatter (warp per edge) ----------
__global__ void k_att3() {
    int w = (blockIdx.x * blockDim.x + threadIdx.x) >> 5;
    if (w >= MT) return;
    int lane = threadIdx.x & 31;
    int s, d;
    if (w < NE) { s = d_src[w]; d = d_dst[w]; }
    else        { s = w - NE; d = s; }
    float a = d_alpha[w] / d_denom[d];
    int k0 = lane * 4;
    float4 vl = *(const float4*)(d_xlr + (size_t)s * 256 + k0);
    float4 r = make_float4(vl.x * a, vl.y * a, vl.z * a, vl.w * a);
    atomicAdd((float4*)(d_outn + (size_t)d * OD) + lane, r);
}

// ---------------- mean pool by graph ----------------
__global__ void k_pool(const float* __restrict__ bias2) {
    int w = (blockIdx.x * blockDim.x + threadIdx.x) >> 5;
    if (w >= NN) return;
    int lane = threadIdx.x & 31;
    int b = d_bat[w];
    int k0 = lane * 4;
    float4 o = *(const float4*)(d_outn + (size_t)w * OD + k0);
    o.x += bias2[k0]; o.y += bias2[k0 + 1]; o.z += bias2[k0 + 2]; o.w += bias2[k0 + 3];
    atomicAdd((float4*)(d_gsum + (size_t)b * OD) + lane, o);
    if (lane == 0) atomicAdd(&d_gcnt[b], 1.0f);
}

// ---------------- FFN head: y = gelu(g@W1+b1)@W2 + b2 ----------------
__global__ void k_ffn(const float* __restrict__ W1, const float* __restrict__ b1,
                      const float* __restrict__ W2, const float* __restrict__ b2,
                      float* __restrict__ y) {
    __shared__ float g[OD];
    __shared__ float red[128];
    int b = blockIdx.x, t = threadIdx.x;
    float inv = 1.0f / fmaxf(d_gcnt[b], 1.0f);
    g[t] = d_gsum[b * OD + t] * inv;
    __syncthreads();
    float part = 0.0f;
#pragma unroll
    for (int q = 0; q < 4; q++) {
        int j = t + q * 128;
        float acc = b1[j];
        for (int k = 0; k < OD; k++) acc = fmaf(g[k], W1[k * 512 + j], acc);
        part = fmaf(gelu_t(acc), W2[j], part);
    }
    red[t] = part;
    __syncthreads();
    for (int o = 64; o; o >>= 1) {
        if (t < o) red[t] += red[t + o];
        __syncthreads();
    }
    if (t == 0) y[b] = red[0] + b2[0];
}

// ---------------- launch ----------------
static void* g_ptr[8];
static int g_init = 0;

extern "C" void kernel_launch(void* const* d_in, const int* in_sizes, int n_in,
                              void* d_out, int out_size) {
    (void)in_sizes; (void)n_in; (void)out_size;
    const float* x     = (const float*)d_in[0];
    const int*   ei    = (const int*)d_in[1];
    const float* ea    = (const float*)d_in[2];
    const int*   bat   = (const int*)d_in[3];
    const float* Wmsg  = (const float*)d_in[4];
    const float* bmsg  = (const float*)d_in[5];
    const float* We1   = (const float*)d_in[6];
    const float* be1   = (const float*)d_in[7];
    const float* Wself = (const float*)d_in[8];
    const float* bself = (const float*)d_in[9];
    const float* Wl    = (const float*)d_in[10];
    const float* bl    = (const float*)d_in[11];
    const float* Wr    = (const float*)d_in[12];
    const float* br    = (const float*)d_in[13];
    const float* We2   = (const float*)d_in[14];
    const float* att   = (const float*)d_in[15];
    const float* bias2 = (const float*)d_in[16];
    const float* W1    = (const float*)d_in[17];
    const float* b1    = (const float*)d_in[18];
    const float* W2    = (const float*)d_in[19];
    const float* b2    = (const float*)d_in[20];
    float* y = (float*)d_out;

    if (!g_init) {
        cudaGetSymbolAddress(&g_ptr[0], d_xagg);
        cudaGetSymbolAddress(&g_ptr[1], d_easum);
        cudaGetSymbolAddress(&g_ptr[2], d_deg);
        cudaGetSymbolAddress(&g_ptr[3], d_denom);
        cudaGetSymbolAddress(&g_ptr[4], d_outn);
        cudaGetSymbolAddress(&g_ptr[5], d_gsum);
        cudaGetSymbolAddress(&g_ptr[6], d_gcnt);
        cudaGetSymbolAddress(&g_ptr[7], d_amax);
        g_init = 1;
    }
    cudaMemsetAsync(g_ptr[0], 0, sizeof(float) * NN * FIN);
    cudaMemsetAsync(g_ptr[1], 0, sizeof(float) * NN * FE);
    cudaMemsetAsync(g_ptr[2], 0, sizeof(float) * NN);
    cudaMemsetAsync(g_ptr[3], 0, sizeof(float) * NN);
    cudaMemsetAsync(g_ptr[4], 0, sizeof(float) * (size_t)NN * OD);
    cudaMemsetAsync(g_ptr[5], 0, sizeof(float) * NG * OD);
    cudaMemsetAsync(g_ptr[6], 0, sizeof(float) * NG);
    cudaMemsetAsync(g_ptr[7], 0xFF, sizeof(unsigned) * NN);

    k_detect<<<1, 1>>>(ei);
    k_convert<<<(NE + 255) / 256, 256>>>(ei, bat);
    k_scatter<<<NE / 8, 256>>>(x, ea);
    k_packw<<<(HD * 2 * OD + 255) / 256, 256>>>(Wmsg, Wself, We1, Wl, bl, Wr, br);
    k_packxin<<<(NN * K1 + 255) / 256, 256>>>(x);
    dim3 gg(NN / 64, 4);
    k_gemm<0, K1><<<gg, 256>>>(bmsg, be1, bself);
    k_gemm<1, HD><<<gg, 256>>>(nullptr, nullptr, nullptr);
    k_att1<<<MT / 8, 256>>>(ea, We2, att);
    k_att2<<<(MT + 255) / 256, 256>>>();
    k_att3<<<MT / 8, 256>>>();
    k_pool<<<NN / 8, 256>>>(bias2);
    k_ffn<<<NG, 128>>>(W1, b1, W2, b2, y);
}

// round 4
// speedup vs baseline: 1.1309x; 1.1309x over previous
#include <cuda_runtime.h>
#include <math.h>
#include <stdint.h>

#define NN 40000
#define NE 640000
#define FIN 64
#define FE 16
#define NG 1000
#define HD 256
#define OD 128
#define MT (NE + NN)      // edges + self loops = 680000

// ---------------- scratch (device globals; no runtime allocation) ----------
__device__ __align__(16) int   d_src[NE];
__device__ __align__(16) int   d_dst[NE];
__device__ __align__(16) int   d_bat[NN];
__device__            int      d_flag64;
__device__ __align__(16) float d_xagg[NN * FIN];
__device__ __align__(16) float d_easum[NN * FE];
__device__ __align__(16) float d_deg[NN];
__device__ __align__(16) float d_Wcat[144 * HD];
__device__ __align__(16) float d_h[(size_t)NN * HD];
__device__ __align__(16) float d_Wlr[HD * 2 * OD];
__device__ __align__(16) float d_blr[2 * OD];
__device__ __align__(16) float d_xlr[(size_t)NN * 2 * OD];
__device__ __align__(16) float d_alpha[MT];
__device__ __align__(16) unsigned d_amax[NN];
__device__ __align__(16) float d_denom[NN];
__device__ __align__(16) float d_outn[(size_t)NN * OD];
__device__ __align__(16) float d_gsum[NG * OD];
__device__ __align__(16) float d_gcnt[NG];

// ---------------- helpers ----------------
__device__ __forceinline__ float gelu_t(float x) {
    float u = 0.7978845608028654f * (x + 0.044715f * x * x * x);
    return 0.5f * x * (1.0f + tanhf(u));
}

__device__ __forceinline__ void atomicMaxF(unsigned* addr, float v) {
    if (v >= 0.0f) atomicMax((int*)addr, __float_as_int(v));
    else           atomicMin(addr, __float_as_uint(v));
}

// ---------------- one-shot zero/init of all accumulators ----------------
__global__ void k_zero() {
    const float4 z = make_float4(0.f, 0.f, 0.f, 0.f);
    unsigned i = blockIdx.x * blockDim.x + threadIdx.x;
    unsigned st = gridDim.x * blockDim.x;
    for (unsigned j = i; j < NN * FIN / 4; j += st) ((float4*)d_xagg)[j] = z;
    for (unsigned j = i; j < NN * FE / 4; j += st) ((float4*)d_easum)[j] = z;
    for (unsigned j = i; j < NN / 4; j += st) {
        ((float4*)d_deg)[j] = z;
        ((float4*)d_denom)[j] = z;
        uint4 m; m.x = m.y = m.z = m.w = 0xFF800000u;   // -inf bits
        ((uint4*)d_amax)[j] = m;
    }
    for (unsigned j = i; j < (unsigned)NN * OD / 4; j += st) ((float4*)d_outn)[j] = z;
    for (unsigned j = i; j < NG * OD / 4; j += st) ((float4*)d_gsum)[j] = z;
    for (unsigned j = i; j < NG / 4; j += st) ((float4*)d_gcnt)[j] = z;
}

// ---------------- index dtype sniff + normalize ----------------
__global__ void k_detect(const int* __restrict__ ei) {
    int allz = 1;
    for (int i = 1; i < 64; i += 2) if (ei[i] != 0) allz = 0;
    d_flag64 = allz;
}

__global__ void k_convert(const int* __restrict__ ei, const int* __restrict__ bat) {
    int i = blockIdx.x * blockDim.x + threadIdx.x;
    int f = d_flag64;
    if (i < NE) {
        if (f) { d_src[i] = ei[2 * i]; d_dst[i] = ei[2 * (NE + i)]; }
        else   { d_src[i] = ei[i];     d_dst[i] = ei[NE + i]; }
    }
    if (i < NN) d_bat[i] = f ? bat[2 * i] : bat[i];
}

// ---------------- layer-1 edge scatter (half-warp per edge) ----------
__global__ void k_scatter(const float* __restrict__ x, const float* __restrict__ ea) {
    int hw = (blockIdx.x * blockDim.x + threadIdx.x) >> 4;
    if (hw >= NE) return;
    int l = threadIdx.x & 15;
    int s = d_src[hw], d = d_dst[hw];
    float4 v = __ldg((const float4*)(x + (size_t)s * FIN) + l);
    atomicAdd((float4*)(d_xagg + (size_t)d * FIN) + l, v);
    if (l < 4) {
        float4 e = __ldg((const float4*)(ea + (size_t)hw * FE) + l);
        atomicAdd((float4*)(d_easum + (size_t)d * FE) + l, e);
    }
    if (l == 0) atomicAdd(&d_deg[d], 1.0f);
}

// ---------------- pack fused weights (float4) ----------------
__global__ void k_packw(const float* __restrict__ Wmsg, const float* __restrict__ Wself,
                        const float* __restrict__ We1, const float* __restrict__ Wl,
                        const float* __restrict__ bl, const float* __restrict__ Wr,
                        const float* __restrict__ br) {
    int i = blockIdx.x * blockDim.x + threadIdx.x;   // float4 index
    // d_Wcat: 144*256 floats = 9216 float4 (boundaries at 4096 / 8192)
    if (i < 4096)       ((float4*)d_Wcat)[i] = ((const float4*)Wmsg)[i];
    else if (i < 8192)  ((float4*)d_Wcat)[i] = ((const float4*)Wself)[i - 4096];
    else if (i < 9216)  ((float4*)d_Wcat)[i] = ((const float4*)We1)[i - 8192];
    // d_Wlr: 256*256 floats = 16384? no: 256 rows * 256 cols /4 = 16384 float4
    if (i < 16384) {
        int k = i >> 6, c4 = i & 63;
        ((float4*)d_Wlr)[i] = (c4 < 32) ? ((const float4*)Wl)[k * 32 + c4]
                                        : ((const float4*)Wr)[k * 32 + (c4 - 32)];
    }
    if (i < 64) ((float4*)d_blr)[i] = (i < 32) ? ((const float4*)bl)[i]
                                               : ((const float4*)br)[i - 32];
}

// ---------------- fp32 SGEMM: 128x64 tile, 256 thr, 8x4 micro, dbl-buffer --
// MODE 0: h   = gelu(A1@Wcat + deg*(b_msg+b_edge1) + b_self), K=144,
//         A1 row r = [xagg[r] | x[r] | easum[r]]  (gathered on the fly)
// MODE 1: xlr = h@Wlr + blr, K=256
template <int MODE>
__global__ void __launch_bounds__(256, 3)
k_gemm(const float* __restrict__ x, const float* __restrict__ bm,
       const float* __restrict__ be1, const float* __restrict__ bs) {
    constexpr int K = (MODE == 0) ? 144 : 256;
    __shared__ float As[2][16][132];
    __shared__ float Bs[2][16][64];
    const float* B = (MODE == 0) ? d_Wcat : d_Wlr;
    float* C       = (MODE == 0) ? d_h : d_xlr;

    const int r0 = blockIdx.x * 128, c0 = blockIdx.y * 64;
    const int t = threadIdx.x;
    const int tx = t & 15, ty = t >> 4;      // tx: 4 cols, ty: 8 rows

    // A loader: row = t>>1, two float4 at k-offsets ak and ak+8 (ak in {0,4})
    const int ar = t >> 1;
    const int ak = (t & 1) * 4;
    int arow = r0 + ar; if (arow >= NN) arow = NN - 1;
    // B loader: row t>>4, float4 at col (t&15)*4
    const int brw = t >> 4;
    const int bc = (t & 15) * 4;

    float acc[8][4];
#pragma unroll
    for (int i = 0; i < 8; i++)
#pragma unroll
        for (int j = 0; j < 4; j++) acc[i][j] = 0.0f;

    float4 a0, a1, b0;
    // fetch helper (MODE 0 gathers from 3 regions; each 16-tile is uniform)
    auto fetchA = [&](int kt, float4& u0, float4& u1) {
        const float* p;
        int k = kt + ak;
        if (MODE == 0) {
            if (k < 64)       p = d_xagg + (size_t)arow * 64 + k;
            else if (k < 128) p = x + (size_t)arow * 64 + (k - 64);
            else              p = d_easum + (size_t)arow * 16 + (k - 128);
        } else {
            p = d_h + (size_t)arow * 256 + k;
        }
        u0 = *(const float4*)p;
        u1 = *(const float4*)(p + 8);
    };
    auto stageA = [&](int buf, const float4& u0, const float4& u1) {
        As[buf][ak + 0][ar] = u0.x; As[buf][ak + 1][ar] = u0.y;
        As[buf][ak + 2][ar] = u0.z; As[buf][ak + 3][ar] = u0.w;
        As[buf][ak + 8][ar] = u1.x; As[buf][ak + 9][ar] = u1.y;
        As[buf][ak + 10][ar] = u1.z; As[buf][ak + 11][ar] = u1.w;
    };

    fetchA(0, a0, a1);
    b0 = *(const float4*)(B + (size_t)brw * 256 + c0 + bc);
    stageA(0, a0, a1);
    *(float4*)(&Bs[0][brw][bc]) = b0;
    __syncthreads();

    int buf = 0;
    for (int kt = 16; kt < K; kt += 16) {
        fetchA(kt, a0, a1);
        b0 = *(const float4*)(B + (size_t)(kt + brw) * 256 + c0 + bc);
#pragma unroll
        for (int kk = 0; kk < 16; kk++) {
            float4 av0 = *(const float4*)(&As[buf][kk][ty * 8]);
            float4 av1 = *(const float4*)(&As[buf][kk][ty * 8 + 4]);
            float4 bv  = *(const float4*)(&Bs[buf][kk][tx * 4]);
            float arr[8] = {av0.x, av0.y, av0.z, av0.w, av1.x, av1.y, av1.z, av1.w};
            float brr[4] = {bv.x, bv.y, bv.z, bv.w};
#pragma unroll
            for (int i = 0; i < 8; i++)
#pragma unroll
                for (int j = 0; j < 4; j++)
                    acc[i][j] = fmaf(arr[i], brr[j], acc[i][j]);
        }
        buf ^= 1;
        stageA(buf, a0, a1);
        *(float4*)(&Bs[buf][brw][bc]) = b0;
        __syncthreads();
    }
#pragma unroll
    for (int kk = 0; kk < 16; kk++) {
        float4 av0 = *(const float4*)(&As[buf][kk][ty * 8]);
        float4 av1 = *(const float4*)(&As[buf][kk][ty * 8 + 4]);
        float4 bv  = *(const float4*)(&Bs[buf][kk][tx * 4]);
        float arr[8] = {av0.x, av0.y, av0.z, av0.w, av1.x, av1.y, av1.z, av1.w};
        float brr[4] = {bv.x, bv.y, bv.z, bv.w};
#pragma unroll
        for (int i = 0; i < 8; i++)
#pragma unroll
            for (int j = 0; j < 4; j++)
                acc[i][j] = fmaf(arr[i], brr[j], acc[i][j]);
    }

    // epilogue
    float cb[4], sb[4];
#pragma unroll
    for (int j = 0; j < 4; j++) {
        int col = c0 + tx * 4 + j;
        if (MODE == 0) { cb[j] = bm[col] + be1[col]; sb[j] = bs[col]; }
        else           { cb[j] = 0.0f;               sb[j] = d_blr[col]; }
    }
#pragma unroll
    for (int i = 0; i < 8; i++) {
        int row = r0 + ty * 8 + i;
        if (row < NN) {
            float dg = (MODE == 0) ? d_deg[row] : 0.0f;
            float4 o;
            float v0 = acc[i][0] + dg * cb[0] + sb[0];
            float v1 = acc[i][1] + dg * cb[1] + sb[1];
            float v2 = acc[i][2] + dg * cb[2] + sb[2];
            float v3 = acc[i][3] + dg * cb[3] + sb[3];
            if (MODE == 0) {
                o = make_float4(gelu_t(v0), gelu_t(v1), gelu_t(v2), gelu_t(v3));
            } else {
                o = make_float4(v0, v1, v2, v3);
            }
            *(float4*)(&C[(size_t)row * 256 + c0 + tx * 4]) = o;
        }
    }
}

// ---------------- GATv2 pass 1: alpha + segment max (warp per edge) -------
__global__ void k_att1(const float* __restrict__ ea, const float* __restrict__ We2,
                       const float* __restrict__ att) {
    __shared__ float sW[FE * OD];
    __shared__ float sA[OD];
    for (int i = threadIdx.x; i < FE * OD; i += blockDim.x) sW[i] = We2[i];
    for (int i = threadIdx.x; i < OD; i += blockDim.x) sA[i] = att[i];
    __syncthreads();

    int w = (blockIdx.x * blockDim.x + threadIdx.x) >> 5;
    if (w >= MT) return;
    int lane = threadIdx.x & 31;

    int s, d;
    float ear[FE];
    if (w < NE) {
        s = d_src[w]; d = d_dst[w];
        const float4* p4 = (const float4*)(ea + (size_t)w * FE);
#pragma unroll
        for (int q = 0; q < 4; q++) {
            float4 e = __ldg(p4 + q);
            ear[q * 4 + 0] = e.x; ear[q * 4 + 1] = e.y;
            ear[q * 4 + 2] = e.z; ear[q * 4 + 3] = e.w;
        }
    } else {
        int v = w - NE; s = v; d = v;
        float inv = 1.0f / fmaxf(d_deg[v], 1.0f);
        const float4* p4 = (const float4*)(d_easum + (size_t)v * FE);
#pragma unroll
        for (int q = 0; q < 4; q++) {
            float4 e = p4[q];
            ear[q * 4 + 0] = e.x * inv; ear[q * 4 + 1] = e.y * inv;
            ear[q * 4 + 2] = e.z * inv; ear[q * 4 + 3] = e.w * inv;
        }
    }

    int k0 = lane * 4;
    float4 vl = *(const float4*)(d_xlr + (size_t)s * 256 + k0);
    float4 vr = *(const float4*)(d_xlr + (size_t)d * 256 + 128 + k0);
    float m0 = vl.x + vr.x, m1 = vl.y + vr.y, m2 = vl.z + vr.z, m3 = vl.w + vr.w;
#pragma unroll
    for (int i = 0; i < FE; i++) {
        float e = ear[i];
        float4 wv = *(const float4*)(&sW[i * OD + k0]);
        m0 = fmaf(e, wv.x, m0); m1 = fmaf(e, wv.y, m1);
        m2 = fmaf(e, wv.z, m2); m3 = fmaf(e, wv.w, m3);
    }
    m0 = m0 > 0.f ? m0 : 0.2f * m0;
    m1 = m1 > 0.f ? m1 : 0.2f * m1;
    m2 = m2 > 0.f ? m2 : 0.2f * m2;
    m3 = m3 > 0.f ? m3 : 0.2f * m3;
    float4 a4 = *(const float4*)(&sA[k0]);
    float a = m0 * a4.x + m1 * a4.y + m2 * a4.z + m3 * a4.w;
#pragma unroll
    for (int o = 16; o; o >>= 1) a += __shfl_xor_sync(0xFFFFFFFFu, a, o);
    if (lane == 0) {
        d_alpha[w] = a;
        atomicMaxF(&d_amax[d], a);
    }
}

// ---------------- GATv2 pass 2: exp + denom ----------------
__global__ void k_att2() {
    int m = blockIdx.x * blockDim.x + threadIdx.x;
    if (m >= MT) return;
    int d = (m < NE) ? d_dst[m] : (m - NE);
    float amax = __uint_as_float(d_amax[d]);
    float wv = __expf(d_alpha[m] - amax);
    d_alpha[m] = wv;
    atomicAdd(&d_denom[d], wv);
}

// ---------------- GATv2 pass 3: weighted scatter (warp per edge) ----------
__global__ void k_att3() {
    int w = (blockIdx.x * blockDim.x + threadIdx.x) >> 5;
    if (w >= MT) return;
    int lane = threadIdx.x & 31;
    int s, d;
    if (w < NE) { s = d_src[w]; d = d_dst[w]; }
    else        { s = w - NE; d = s; }
    float a = d_alpha[w] / d_denom[d];
    int k0 = lane * 4;
    float4 vl = *(const float4*)(d_xlr + (size_t)s * 256 + k0);
    float4 r = make_float4(vl.x * a, vl.y * a, vl.z * a, vl.w * a);
    atomicAdd((float4*)(d_outn + (size_t)d * OD) + lane, r);
}

// ---------------- mean pool by graph ----------------
__global__ void k_pool(const float* __restrict__ bias2) {
    int w = (blockIdx.x * blockDim.x + threadIdx.x) >> 5;
    if (w >= NN) return;
    int lane = threadIdx.x & 31;
    int b = d_bat[w];
    int k0 = lane * 4;
    float4 o = *(const float4*)(d_outn + (size_t)w * OD + k0);
    o.x += bias2[k0]; o.y += bias2[k0 + 1]; o.z += bias2[k0 + 2]; o.w += bias2[k0 + 3];
    atomicAdd((float4*)(d_gsum + (size_t)b * OD) + lane, o);
    if (lane == 0) atomicAdd(&d_gcnt[b], 1.0f);
}

// ---------------- FFN head: y = gelu(g@W1+b1)@W2 + b2 ----------------
__global__ void k_ffn(const float* __restrict__ W1, const float* __restrict__ b1,
                      const float* __restrict__ W2, const float* __restrict__ b2,
                      float* __restrict__ y) {
    __shared__ float g[OD];
    __shared__ float red[128];
    int b = blockIdx.x, t = threadIdx.x;
    float inv = 1.0f / fmaxf(d_gcnt[b], 1.0f);
    g[t] = d_gsum[b * OD + t] * inv;
    __syncthreads();
    float part = 0.0f;
#pragma unroll
    for (int q = 0; q < 4; q++) {
        int j = t + q * 128;
        float acc = b1[j];
        for (int k = 0; k < OD; k++) acc = fmaf(g[k], W1[k * 512 + j], acc);
        part = fmaf(gelu_t(acc), W2[j], part);
    }
    red[t] = part;
    __syncthreads();
    for (int o = 64; o; o >>= 1) {
        if (t < o) red[t] += red[t + o];
        __syncthreads();
    }
    if (t == 0) y[b] = red[0] + b2[0];
}

// ---------------- launch ----------------
extern "C" void kernel_launch(void* const* d_in, const int* in_sizes, int n_in,
                              void* d_out, int out_size) {
    (void)in_sizes; (void)n_in; (void)out_size;
    const float* x     = (const float*)d_in[0];
    const int*   ei    = (const int*)d_in[1];
    const float* ea    = (const float*)d_in[2];
    const int*   bat   = (const int*)d_in[3];
    const float* Wmsg  = (const float*)d_in[4];
    const float* bmsg  = (const float*)d_in[5];
    const float* We1   = (const float*)d_in[6];
    const float* be1   = (const float*)d_in[7];
    const float* Wself = (const float*)d_in[8];
    const float* bself = (const float*)d_in[9];
    const float* Wl    = (const float*)d_in[10];
    const float* bl    = (const float*)d_in[11];
    const float* Wr    = (const float*)d_in[12];
    const float* br    = (const float*)d_in[13];
    const float* We2   = (const float*)d_in[14];
    const float* att   = (const float*)d_in[15];
    const float* bias2 = (const float*)d_in[16];
    const float* W1    = (const float*)d_in[17];
    const float* b1    = (const float*)d_in[18];
    const float* W2    = (const float*)d_in[19];
    const float* b2    = (const float*)d_in[20];
    float* y = (float*)d_out;

    k_zero<<<2048, 256>>>();
    k_detect<<<1, 1>>>(ei);
    k_convert<<<(NE + 255) / 256, 256>>>(ei, bat);
    k_scatter<<<NE / 16, 256>>>(x, ea);
    k_packw<<<16384 / 256, 256>>>(Wmsg, Wself, We1, Wl, bl, Wr, br);
    dim3 gg((NN + 127) / 128, 4);
    k_gemm<0><<<gg, 256>>>(x, bmsg, be1, bself);
    k_gemm<1><<<gg, 256>>>(x, nullptr, nullptr, nullptr);
    k_att1<<<MT / 8, 256>>>(ea, We2, att);
    k_att2<<<(MT + 255) / 256, 256>>>();
    k_att3<<<MT / 8, 256>>>();
    k_pool<<<NN / 8, 256>>>(bias2);
    k_ffn<<<NG, 128>>>(W1, b1, W2, b2, y);
}

// round 9
// speedup vs baseline: 1.2814x; 1.1330x over previous
#include <cuda_runtime.h>
#include <math.h>
#include <stdint.h>

#define NN 40000
#define NE 640000
#define FIN 64
#define FE 16
#define NG 1000
#define HD 256
#define OD 128
#define MT (NE + NN)

// ---------------- scratch (device globals) ----------------
__device__ __align__(16) int   d_src[NE];
__device__ __align__(16) int   d_dst[NE];
__device__ __align__(16) int   d_bat[NN];
__device__            int      d_flag64;
__device__ __align__(16) int   d_cnt[NN];
__device__ __align__(16) int   d_cursor[NN];
__device__ __align__(16) int   d_rowptr[NN + 1];
__device__ __align__(16) int   d_csrc[NE];
__device__ __align__(16) int   d_ceid[NE];
__device__ __align__(16) float d_xagg[NN * FIN];
__device__ __align__(16) float d_easum[NN * FE];
__device__ __align__(16) float d_deg[NN];
__device__ __align__(16) float d_Wcat[144 * HD];
__device__ __align__(16) float d_h[(size_t)NN * HD];
__device__ __align__(16) float d_Wlr[HD * 2 * OD];
__device__ __align__(16) float d_blr[2 * OD];
__device__ __align__(16) float d_xlr[(size_t)NN * 2 * OD];
__device__ __align__(16) float d_alpha[MT];
__device__ __align__(16) float d_gsum[NG * OD];
__device__ __align__(16) float d_gcnt[NG];

// ---------------- helpers ----------------
__device__ __forceinline__ float gelu_t(float x) {
    float u = 0.7978845608028654f * (x + 0.044715f * x * x * x);
    return 0.5f * x * (1.0f + tanhf(u));
}

// ---------------- zero the small accumulators ----------------
__global__ void k_zero() {
    unsigned i = blockIdx.x * blockDim.x + threadIdx.x;
    unsigned st = gridDim.x * blockDim.x;
    for (unsigned j = i; j < NN; j += st) { d_cnt[j] = 0; d_cursor[j] = 0; }
    for (unsigned j = i; j < NG * OD; j += st) d_gsum[j] = 0.0f;
    for (unsigned j = i; j < NG; j += st) d_gcnt[j] = 0.0f;
}

// ---------------- index dtype sniff ----------------
__global__ void k_detect(const int* __restrict__ ei) {
    int allz = 1;
    for (int i = 1; i < 64; i += 2) if (ei[i] != 0) allz = 0;
    d_flag64 = allz;
}

// ---------------- convert indices + dst histogram ----------------
__global__ void k_convert(const int* __restrict__ ei, const int* __restrict__ bat) {
    int i = blockIdx.x * blockDim.x + threadIdx.x;
    int f = d_flag64;
    if (i < NE) {
        int s, d;
        if (f) { s = ei[2 * i]; d = ei[2 * (NE + i)]; }
        else   { s = ei[i];     d = ei[NE + i]; }
        d_src[i] = s; d_dst[i] = d;
        atomicAdd(&d_cnt[d], 1);
    }
    if (i < NN) d_bat[i] = f ? bat[2 * i] : bat[i];
}

// ---------------- single-block exclusive scan over d_cnt -> d_rowptr ------
__global__ void k_scan() {
    __shared__ int s[1024];
    const int t = threadIdx.x;
    const int PER = (NN + 1023) / 1024;   // 40
    int base = t * PER;
    int sum = 0;
    for (int i = 0; i < PER; i++) {
        int idx = base + i;
        if (idx < NN) sum += d_cnt[idx];
    }
    s[t] = sum;
    __syncthreads();
    for (int o = 1; o < 1024; o <<= 1) {
        int v = (t >= o) ? s[t - o] : 0;
        __syncthreads();
        s[t] += v;
        __syncthreads();
    }
    int run = (t == 0) ? 0 : s[t - 1];
    for (int i = 0; i < PER; i++) {
        int idx = base + i;
        if (idx < NN) { d_rowptr[idx] = run; run += d_cnt[idx]; }
    }
    if (t == 1023) d_rowptr[NN] = NE;
}

// ---------------- scatter edge ids into CSR order ----------------
__global__ void k_scatcsr() {
    int i = blockIdx.x * blockDim.x + threadIdx.x;
    if (i >= NE) return;
    int d = d_dst[i];
    int pos = d_rowptr[d] + atomicAdd(&d_cursor[d], 1);
    d_csrc[pos] = d_src[i];
    d_ceid[pos] = i;
}

// ---------------- layer-1 gather (warp per dst node, no atomics) ----------
__global__ void k_gather(const float* __restrict__ x, const float* __restrict__ ea) {
    int w = (blockIdx.x * blockDim.x + threadIdx.x) >> 5;
    if (w >= NN) return;
    int lane = threadIdx.x & 31;
    int b = d_rowptr[w], e = d_rowptr[w + 1];
    float2 xs = make_float2(0.f, 0.f);
    float es = 0.f;
    for (int i = b; i < e; i++) {
        int s = d_csrc[i];
        float2 v = __ldg((const float2*)(x + (size_t)s * FIN) + lane);
        xs.x += v.x; xs.y += v.y;
        if (lane < FE) {
            int eid = d_ceid[i];
            es += __ldg(ea + (size_t)eid * FE + lane);
        }
    }
    ((float2*)(d_xagg + (size_t)w * FIN))[lane] = xs;
    if (lane < FE) d_easum[w * FE + lane] = es;
    if (lane == 0) d_deg[w] = (float)(e - b);
}

// ---------------- pack fused weights (float4) ----------------
__global__ void k_packw(const float* __restrict__ Wmsg, const float* __restrict__ Wself,
                        const float* __restrict__ We1, const float* __restrict__ Wl,
                        const float* __restrict__ bl, const float* __restrict__ Wr,
                        const float* __restrict__ br) {
    int i = blockIdx.x * blockDim.x + threadIdx.x;   // float4 index
    if (i < 4096)       ((float4*)d_Wcat)[i] = ((const float4*)Wmsg)[i];
    else if (i < 8192)  ((float4*)d_Wcat)[i] = ((const float4*)Wself)[i - 4096];
    else if (i < 9216)  ((float4*)d_Wcat)[i] = ((const float4*)We1)[i - 8192];
    if (i < 16384) {
        int k = i >> 6, c4 = i & 63;
        ((float4*)d_Wlr)[i] = (c4 < 32) ? ((const float4*)Wl)[k * 32 + c4]
                                        : ((const float4*)Wr)[k * 32 + (c4 - 32)];
    }
    if (i < 64) ((float4*)d_blr)[i] = (i < 32) ? ((const float4*)bl)[i]
                                               : ((const float4*)br)[i - 32];
}

// ---------------- fp32 SGEMM: 128x64 tile, 256 thr, 8x4 micro, dbl-buffer --
template <int MODE>
__global__ void __launch_bounds__(256, 3)
k_gemm(const float* __restrict__ x, const float* __restrict__ bm,
       const float* __restrict__ be1, const float* __restrict__ bs) {
    constexpr int K = (MODE == 0) ? 144 : 256;
    __shared__ float As[2][16][132];
    __shared__ float Bs[2][16][64];
    const float* B = (MODE == 0) ? d_Wcat : d_Wlr;
    float* C       = (MODE == 0) ? d_h : d_xlr;

    const int r0 = blockIdx.x * 128, c0 = blockIdx.y * 64;
    const int t = threadIdx.x;
    const int tx = t & 15, ty = t >> 4;

    const int ar = t >> 1;
    const int ak = (t & 1) * 4;
    int arow = r0 + ar; if (arow >= NN) arow = NN - 1;
    const int brw = t >> 4;
    const int bc = (t & 15) * 4;

    float acc[8][4];
#pragma unroll
    for (int i = 0; i < 8; i++)
#pragma unroll
        for (int j = 0; j < 4; j++) acc[i][j] = 0.0f;

    float4 a0, a1, b0;
    auto fetchA = [&](int kt, float4& u0, float4& u1) {
        const float* p;
        int k = kt + ak;
        if (MODE == 0) {
            if (k < 64)       p = d_xagg + (size_t)arow * 64 + k;
            else if (k < 128) p = x + (size_t)arow * 64 + (k - 64);
            else              p = d_easum + (size_t)arow * 16 + (k - 128);
        } else {
            p = d_h + (size_t)arow * 256 + k;
        }
        u0 = *(const float4*)p;
        u1 = *(const float4*)(p + 8);
    };
    auto stageA = [&](int buf, const float4& u0, const float4& u1) {
        As[buf][ak + 0][ar] = u0.x; As[buf][ak + 1][ar] = u0.y;
        As[buf][ak + 2][ar] = u0.z; As[buf][ak + 3][ar] = u0.w;
        As[buf][ak + 8][ar] = u1.x; As[buf][ak + 9][ar] = u1.y;
        As[buf][ak + 10][ar] = u1.z; As[buf][ak + 11][ar] = u1.w;
    };

    fetchA(0, a0, a1);
    b0 = *(const float4*)(B + (size_t)brw * 256 + c0 + bc);
    stageA(0, a0, a1);
    *(float4*)(&Bs[0][brw][bc]) = b0;
    __syncthreads();

    int buf = 0;
    for (int kt = 16; kt < K; kt += 16) {
        fetchA(kt, a0, a1);
        b0 = *(const float4*)(B + (size_t)(kt + brw) * 256 + c0 + bc);
#pragma unroll
        for (int kk = 0; kk < 16; kk++) {
            float4 av0 = *(const float4*)(&As[buf][kk][ty * 8]);
            float4 av1 = *(const float4*)(&As[buf][kk][ty * 8 + 4]);
            float4 bv  = *(const float4*)(&Bs[buf][kk][tx * 4]);
            float arr[8] = {av0.x, av0.y, av0.z, av0.w, av1.x, av1.y, av1.z, av1.w};
            float brr[4] = {bv.x, bv.y, bv.z, bv.w};
#pragma unroll
            for (int i = 0; i < 8; i++)
#pragma unroll
                for (int j = 0; j < 4; j++)
                    acc[i][j] = fmaf(arr[i], brr[j], acc[i][j]);
        }
        buf ^= 1;
        stageA(buf, a0, a1);
        *(float4*)(&Bs[buf][brw][bc]) = b0;
        __syncthreads();
    }
#pragma unroll
    for (int kk = 0; kk < 16; kk++) {
        float4 av0 = *(const float4*)(&As[buf][kk][ty * 8]);
        float4 av1 = *(const float4*)(&As[buf][kk][ty * 8 + 4]);
        float4 bv  = *(const float4*)(&Bs[buf][kk][tx * 4]);
        float arr[8] = {av0.x, av0.y, av0.z, av0.w, av1.x, av1.y, av1.z, av1.w};
        float brr[4] = {bv.x, bv.y, bv.z, bv.w};
#pragma unroll
        for (int i = 0; i < 8; i++)
#pragma unroll
            for (int j = 0; j < 4; j++)
                acc[i][j] = fmaf(arr[i], brr[j], acc[i][j]);
    }

    float cb[4], sb[4];
#pragma unroll
    for (int j = 0; j < 4; j++) {
        int col = c0 + tx * 4 + j;
        if (MODE == 0) { cb[j] = bm[col] + be1[col]; sb[j] = bs[col]; }
        else           { cb[j] = 0.0f;               sb[j] = d_blr[col]; }
    }
#pragma unroll
    for (int i = 0; i < 8; i++) {
        int row = r0 + ty * 8 + i;
        if (row < NN) {
            float dg = (MODE == 0) ? d_deg[row] : 0.0f;
            float v0 = acc[i][0] + dg * cb[0] + sb[0];
            float v1 = acc[i][1] + dg * cb[1] + sb[1];
            float v2 = acc[i][2] + dg * cb[2] + sb[2];
            float v3 = acc[i][3] + dg * cb[3] + sb[3];
            float4 o;
            if (MODE == 0) o = make_float4(gelu_t(v0), gelu_t(v1), gelu_t(v2), gelu_t(v3));
            else           o = make_float4(v0, v1, v2, v3);
            *(float4*)(&C[(size_t)row * 256 + c0 + tx * 4]) = o;
        }
    }
}

// ---------------- fused GATv2 attention + pool (warp per dst node) --------
__global__ void __launch_bounds__(256)
k_att(const float* __restrict__ ea, const float* __restrict__ We2,
      const float* __restrict__ att, const float* __restrict__ bias2) {
    __shared__ float sW[FE * OD];
    __shared__ float sA[OD];
    for (int i = threadIdx.x; i < FE * OD; i += 256) sW[i] = We2[i];
    for (int i = threadIdx.x; i < OD; i += 256) sA[i] = att[i];
    __syncthreads();

    int w = (blockIdx.x * blockDim.x + threadIdx.x) >> 5;
    if (w >= NN) return;
    int lane = threadIdx.x & 31;
    int k0 = lane * 4;
    int b = d_rowptr[w], e = d_rowptr[w + 1];
    float degf = (float)(e - b);
    float inv_deg = 1.0f / fmaxf(degf, 1.0f);

    float4 vr  = *(const float4*)(d_xlr + (size_t)w * 256 + 128 + k0);
    float4 sAv = *(const float4*)(&sA[k0]);
    float amax = -1e30f;

    // ---- loop 1: alpha per incident edge (i==e is the self-loop) ----
    for (int i = b; i <= e; i++) {
        int s;
        float ear[FE];
        if (i < e) {
            s = d_csrc[i];
            int eid = d_ceid[i];
            const float4* p4 = (const float4*)(ea + (size_t)eid * FE);
#pragma unroll
            for (int q = 0; q < 4; q++) {
                float4 ev = __ldg(p4 + q);
                ear[q * 4 + 0] = ev.x; ear[q * 4 + 1] = ev.y;
                ear[q * 4 + 2] = ev.z; ear[q * 4 + 3] = ev.w;
            }
        } else {
            s = w;
            const float4* p4 = (const float4*)(d_easum + (size_t)w * FE);
#pragma unroll
            for (int q = 0; q < 4; q++) {
                float4 ev = p4[q];
                ear[q * 4 + 0] = ev.x * inv_deg; ear[q * 4 + 1] = ev.y * inv_deg;
                ear[q * 4 + 2] = ev.z * inv_deg; ear[q * 4 + 3] = ev.w * inv_deg;
            }
        }
        float4 xl = *(const float4*)(d_xlr + (size_t)s * 256 + k0);
        float m0 = xl.x + vr.x, m1 = xl.y + vr.y, m2 = xl.z + vr.z, m3 = xl.w + vr.w;
#pragma unroll
        for (int q = 0; q < FE; q++) {
            float ev = ear[q];
            float4 wv = *(const float4*)(&sW[q * OD + k0]);
            m0 = fmaf(ev, wv.x, m0); m1 = fmaf(ev, wv.y, m1);
            m2 = fmaf(ev, wv.z, m2); m3 = fmaf(ev, wv.w, m3);
        }
        m0 = m0 > 0.f ? m0 : 0.2f * m0;
        m1 = m1 > 0.f ? m1 : 0.2f * m1;
        m2 = m2 > 0.f ? m2 : 0.2f * m2;
        m3 = m3 > 0.f ? m3 : 0.2f * m3;
        float a = m0 * sAv.x + m1 * sAv.y + m2 * sAv.z + m3 * sAv.w;
#pragma unroll
        for (int o = 16; o; o >>= 1) a += __shfl_xor_sync(0xFFFFFFFFu, a, o);
        amax = fmaxf(amax, a);
        if (lane == 0) d_alpha[(i < e) ? i : (NE + w)] = a;
    }

    // ---- loop 2: exp, denom, weighted accumulation ----
    float denom = 0.0f;
    float4 out = make_float4(0.f, 0.f, 0.f, 0.f);
    for (int i = b; i <= e; i++) {
        int s = (i < e) ? d_csrc[i] : w;
        float a = d_alpha[(i < e) ? i : (NE + w)];
        float ev = __expf(a - amax);
        denom += ev;
        float4 xl = *(const float4*)(d_xlr + (size_t)s * 256 + k0);
        out.x = fmaf(ev, xl.x, out.x); out.y = fmaf(ev, xl.y, out.y);
        out.z = fmaf(ev, xl.z, out.z); out.w = fmaf(ev, xl.w, out.w);
    }
    float invd = 1.0f / denom;
    float4 bb = *(const float4*)(bias2 + k0);
    out.x = fmaf(out.x, invd, bb.x); out.y = fmaf(out.y, invd, bb.y);
    out.z = fmaf(out.z, invd, bb.z); out.w = fmaf(out.w, invd, bb.w);

    int g = d_bat[w];
    atomicAdd((float4*)(d_gsum + (size_t)g * OD) + lane, out);
    if (lane == 0) atomicAdd(&d_gcnt[g], 1.0f);
}

// ---------------- FFN head ----------------
__global__ void k_ffn(const float* __restrict__ W1, const float* __restrict__ b1,
                      const float* __restrict__ W2, const float* __restrict__ b2,
                      float* __restrict__ y) {
    __shared__ float g[OD];
    __shared__ float red[128];
    int b = blockIdx.x, t = threadIdx.x;
    float inv = 1.0f / fmaxf(d_gcnt[b], 1.0f);
    g[t] = d_gsum[b * OD + t] * inv;
    __syncthreads();
    float part = 0.0f;
#pragma unroll
    for (int q = 0; q < 4; q++) {
        int j = t + q * 128;
        float acc = b1[j];
        for (int k = 0; k < OD; k++) acc = fmaf(g[k], W1[k * 512 + j], acc);
        part = fmaf(gelu_t(acc), W2[j], part);
    }
    red[t] = part;
    __syncthreads();
    for (int o = 64; o; o >>= 1) {
        if (t < o) red[t] += red[t + o];
        __syncthreads();
    }
    if (t == 0) y[b] = red[0] + b2[0];
}

// ---------------- launch ----------------
extern "C" void kernel_launch(void* const* d_in, const int* in_sizes, int n_in,
                              void* d_out, int out_size) {
    (void)in_sizes; (void)n_in; (void)out_size;
    const float* x     = (const float*)d_in[0];
    const int*   ei    = (const int*)d_in[1];
    const float* ea    = (const float*)d_in[2];
    const int*   bat   = (const int*)d_in[3];
    const float* Wmsg  = (const float*)d_in[4];
    const float* bmsg  = (const float*)d_in[5];
    const float* We1   = (const float*)d_in[6];
    const float* be1   = (const float*)d_in[7];
    const float* Wself = (const float*)d_in[8];
    const float* bself = (const float*)d_in[9];
    const float* Wl    = (const float*)d_in[10];
    const float* bl    = (const float*)d_in[11];
    const float* Wr    = (const float*)d_in[12];
    const float* br    = (const float*)d_in[13];
    const float* We2   = (const float*)d_in[14];
    const float* att   = (const float*)d_in[15];
    const float* bias2 = (const float*)d_in[16];
    const float* W1    = (const float*)d_in[17];
    const float* b1    = (const float*)d_in[18];
    const float* W2    = (const float*)d_in[19];
    const float* b2    = (const float*)d_in[20];
    float* y = (float*)d_out;

    k_zero<<<512, 256>>>();
    k_detect<<<1, 1>>>(ei);
    k_convert<<<(NE + 255) / 256, 256>>>(ei, bat);
    k_scan<<<1, 1024>>>();
    k_scatcsr<<<(NE + 255) / 256, 256>>>();
    k_gather<<<NN / 8, 256>>>(x, ea);
    k_packw<<<64, 256>>>(Wmsg, Wself, We1, Wl, bl, Wr, br);
    dim3 gg((NN + 127) / 128, 4);
    k_gemm<0><<<gg, 256>>>(x, bmsg, be1, bself);
    k_gemm<1><<<gg, 256>>>(x, nullptr, nullptr, nullptr);
    k_att<<<NN / 8, 256>>>(ea, We2, att, bias2);
    k_ffn<<<NG, 128>>>(W1, b1, W2, b2, y);
}

// round 12
// speedup vs baseline: 1.3779x; 1.0753x over previous
#include <cuda_runtime.h>
#include <math.h>
#include <stdint.h>

#define NN 40000
#define NE 640000
#define FIN 64
#define FE 16
#define NG 1000
#define HD 256
#define OD 128

#define SCB 256
#define NSCB ((NN + SCB - 1) / SCB)   // 157

// ---------------- scratch (device globals) ----------------
__device__ __align__(16) int   d_src[NE];
__device__ __align__(16) int   d_dst[NE];
__device__ __align__(16) int   d_bat[NN];
__device__            int      d_flag64;
__device__ __align__(16) int   d_cnt[NN];
__device__ __align__(16) int   d_cursor[NN];
__device__ __align__(16) int   d_rowptr[NN + 1];
__device__ __align__(16) int   d_part[NSCB];
__device__ __align__(16) int   d_csrc[NE];
__device__ __align__(16) int   d_ceid[NE];
__device__ __align__(16) float d_xagg[NN * FIN];
__device__ __align__(16) float d_easum[NN * FE];
__device__ __align__(16) float d_deg[NN];
__device__ __align__(16) float d_Wcat[144 * HD];
__device__ __align__(16) float d_h[(size_t)NN * HD];
__device__ __align__(16) float d_Wlr[HD * 2 * OD];
__device__ __align__(16) float d_blr[2 * OD];
__device__ __align__(16) float d_xlr[(size_t)NN * 2 * OD];
__device__ __align__(16) float d_gsum[NG * OD];
__device__ __align__(16) float d_gcnt[NG];

// ---------------- helpers ----------------
__device__ __forceinline__ float gelu_t(float x) {
    float u = 0.7978845608028654f * (x + 0.044715f * x * x * x);
    return 0.5f * x * (1.0f + tanhf(u));
}

// ---------------- zero the small accumulators ----------------
__global__ void k_zero() {
    unsigned i = blockIdx.x * blockDim.x + threadIdx.x;
    unsigned st = gridDim.x * blockDim.x;
    for (unsigned j = i; j < NN; j += st) { d_cnt[j] = 0; d_cursor[j] = 0; }
    for (unsigned j = i; j < NG * OD; j += st) d_gsum[j] = 0.0f;
    for (unsigned j = i; j < NG; j += st) d_gcnt[j] = 0.0f;
}

// ---------------- index dtype sniff ----------------
__global__ void k_detect(const int* __restrict__ ei) {
    int allz = 1;
    for (int i = 1; i < 64; i += 2) if (ei[i] != 0) allz = 0;
    d_flag64 = allz;
}

// ---------------- convert indices + dst histogram ----------------
__global__ void k_convert(const int* __restrict__ ei, const int* __restrict__ bat) {
    int i = blockIdx.x * blockDim.x + threadIdx.x;
    int f = d_flag64;
    if (i < NE) {
        int s, d;
        if (f) { s = ei[2 * i]; d = ei[2 * (NE + i)]; }
        else   { s = ei[i];     d = ei[NE + i]; }
        d_src[i] = s; d_dst[i] = d;
        atomicAdd(&d_cnt[d], 1);
    }
    if (i < NN) d_bat[i] = f ? bat[2 * i] : bat[i];
}

// ---------------- multi-block exclusive scan: phase A (block sums) --------
__global__ void k_scanA() {
    __shared__ int wsum[8];
    int t = threadIdx.x;
    int i = blockIdx.x * SCB + t;
    int v = (i < NN) ? d_cnt[i] : 0;
    int lane = t & 31, wid = t >> 5;
    int s = v;
#pragma unroll
    for (int o = 1; o < 32; o <<= 1) s += __shfl_xor_sync(0xFFFFFFFFu, s, o);
    if (lane == 0) wsum[wid] = s;
    __syncthreads();
    if (t == 0) {
        int r = 0;
#pragma unroll
        for (int k = 0; k < 8; k++) r += wsum[k];
        d_part[blockIdx.x] = r;
    }
}

// ---------------- phase B: scan the 157 partials (1 block) ---------------
__global__ void k_scanB() {
    __shared__ int s[NSCB];
    int t = threadIdx.x;
    if (t < NSCB) s[t] = d_part[t];
    __syncthreads();
    if (t == 0) {
        int r = 0;
        for (int k = 0; k < NSCB; k++) { int v = s[k]; s[k] = r; r += v; }
        d_rowptr[NN] = NE;
    }
    __syncthreads();
    if (t < NSCB) d_part[t] = s[t];
}

// ---------------- phase C: block-local exclusive scan + offset -----------
__global__ void k_scanC() {
    __shared__ int wsum[8];
    int t = threadIdx.x;
    int i = blockIdx.x * SCB + t;
    int v = (i < NN) ? d_cnt[i] : 0;
    int lane = t & 31, wid = t >> 5;
    int x = v;
#pragma unroll
    for (int o = 1; o < 32; o <<= 1) {
        int y = __shfl_up_sync(0xFFFFFFFFu, x, o);
        if (lane >= o) x += y;
    }
    if (lane == 31) wsum[wid] = x;
    __syncthreads();
    if (t == 0) {
        int r = 0;
#pragma unroll
        for (int k = 0; k < 8; k++) { int tmp = wsum[k]; wsum[k] = r; r += tmp; }
    }
    __syncthreads();
    if (i < NN) d_rowptr[i] = d_part[blockIdx.x] + wsum[wid] + x - v;
}

// ---------------- scatter edge ids into CSR order ----------------
__global__ void k_scatcsr() {
    int i = blockIdx.x * blockDim.x + threadIdx.x;
    if (i >= NE) return;
    int d = d_dst[i];
    int pos = d_rowptr[d] + atomicAdd(&d_cursor[d], 1);
    d_csrc[pos] = d_src[i];
    d_ceid[pos] = i;
}

// ---------------- layer-1 gather (warp per dst node, no atomics) ----------
__global__ void k_gather(const float* __restrict__ x, const float* __restrict__ ea) {
    int w = (blockIdx.x * blockDim.x + threadIdx.x) >> 5;
    if (w >= NN) return;
    int lane = threadIdx.x & 31;
    int b = d_rowptr[w], e = d_rowptr[w + 1];
    float2 xs = make_float2(0.f, 0.f);
    float es = 0.f;
    for (int i = b; i < e; i++) {
        int s = d_csrc[i];
        float2 v = __ldg((const float2*)(x + (size_t)s * FIN) + lane);
        xs.x += v.x; xs.y += v.y;
        if (lane < FE) {
            int eid = d_ceid[i];
            es += __ldg(ea + (size_t)eid * FE + lane);
        }
    }
    ((float2*)(d_xagg + (size_t)w * FIN))[lane] = xs;
    if (lane < FE) d_easum[w * FE + lane] = es;
    if (lane == 0) d_deg[w] = (float)(e - b);
}

// ---------------- pack fused weights (float4) ----------------
__global__ void k_packw(const float* __restrict__ Wmsg, const float* __restrict__ Wself,
                        const float* __restrict__ We1, const float* __restrict__ Wl,
                        const float* __restrict__ bl, const float* __restrict__ Wr,
                        const float* __restrict__ br) {
    int i = blockIdx.x * blockDim.x + threadIdx.x;   // float4 index
    if (i < 4096)       ((float4*)d_Wcat)[i] = ((const float4*)Wmsg)[i];
    else if (i < 8192)  ((float4*)d_Wcat)[i] = ((const float4*)Wself)[i - 4096];
    else if (i < 9216)  ((float4*)d_Wcat)[i] = ((const float4*)We1)[i - 8192];
    if (i < 16384) {
        int k = i >> 6, c4 = i & 63;
        ((float4*)d_Wlr)[i] = (c4 < 32) ? ((const float4*)Wl)[k * 32 + c4]
                                        : ((const float4*)Wr)[k * 32 + (c4 - 32)];
    }
    if (i < 64) ((float4*)d_blr)[i] = (i < 32) ? ((const float4*)bl)[i]
                                               : ((const float4*)br)[i - 32];
}

// ---------------- fp32 SGEMM: 128x64 tile, 256 thr, 8x4 micro, dbl-buffer --
template <int MODE>
__global__ void __launch_bounds__(256, 3)
k_gemm(const float* __restrict__ x, const float* __restrict__ bm,
       const float* __restrict__ be1, const float* __restrict__ bs) {
    constexpr int K = (MODE == 0) ? 144 : 256;
    __shared__ float As[2][16][132];
    __shared__ float Bs[2][16][64];
    const float* B = (MODE == 0) ? d_Wcat : d_Wlr;
    float* C       = (MODE == 0) ? d_h : d_xlr;

    const int r0 = blockIdx.x * 128, c0 = blockIdx.y * 64;
    const int t = threadIdx.x;
    const int tx = t & 15, ty = t >> 4;

    const int ar = t >> 1;
    const int ak = (t & 1) * 4;
    int arow = r0 + ar; if (arow >= NN) arow = NN - 1;
    const int brw = t >> 4;
    const int bc = (t & 15) * 4;

    float acc[8][4];
#pragma unroll
    for (int i = 0; i < 8; i++)
#pragma unroll
        for (int j = 0; j < 4; j++) acc[i][j] = 0.0f;

    float4 a0, a1, b0;
    auto fetchA = [&](int kt, float4& u0, float4& u1) {
        const float* p;
        int k = kt + ak;
        if (MODE == 0) {
            if (k < 64)       p = d_xagg + (size_t)arow * 64 + k;
            else if (k < 128) p = x + (size_t)arow * 64 + (k - 64);
            else              p = d_easum + (size_t)arow * 16 + (k - 128);
        } else {
            p = d_h + (size_t)arow * 256 + k;
        }
        u0 = *(const float4*)p;
        u1 = *(const float4*)(p + 8);
    };
    auto stageA = [&](int buf, const float4& u0, const float4& u1) {
        As[buf][ak + 0][ar] = u0.x; As[buf][ak + 1][ar] = u0.y;
        As[buf][ak + 2][ar] = u0.z; As[buf][ak + 3][ar] = u0.w;
        As[buf][ak + 8][ar] = u1.x; As[buf][ak + 9][ar] = u1.y;
        As[buf][ak + 10][ar] = u1.z; As[buf][ak + 11][ar] = u1.w;
    };

    fetchA(0, a0, a1);
    b0 = *(const float4*)(B + (size_t)brw * 256 + c0 + bc);
    stageA(0, a0, a1);
    *(float4*)(&Bs[0][brw][bc]) = b0;
    __syncthreads();

    int buf = 0;
    for (int kt = 16; kt < K; kt += 16) {
        fetchA(kt, a0, a1);
        b0 = *(const float4*)(B + (size_t)(kt + brw) * 256 + c0 + bc);
#pragma unroll
        for (int kk = 0; kk < 16; kk++) {
            float4 av0 = *(const float4*)(&As[buf][kk][ty * 8]);
            float4 av1 = *(const float4*)(&As[buf][kk][ty * 8 + 4]);
            float4 bv  = *(const float4*)(&Bs[buf][kk][tx * 4]);
            float arr[8] = {av0.x, av0.y, av0.z, av0.w, av1.x, av1.y, av1.z, av1.w};
            float brr[4] = {bv.x, bv.y, bv.z, bv.w};
#pragma unroll
            for (int i = 0; i < 8; i++)
#pragma unroll
                for (int j = 0; j < 4; j++)
                    acc[i][j] = fmaf(arr[i], brr[j], acc[i][j]);
        }
        buf ^= 1;
        stageA(buf, a0, a1);
        *(float4*)(&Bs[buf][brw][bc]) = b0;
        __syncthreads();
    }
#pragma unroll
    for (int kk = 0; kk < 16; kk++) {
        float4 av0 = *(const float4*)(&As[buf][kk][ty * 8]);
        float4 av1 = *(const float4*)(&As[buf][kk][ty * 8 + 4]);
        float4 bv  = *(const float4*)(&Bs[buf][kk][tx * 4]);
        float arr[8] = {av0.x, av0.y, av0.z, av0.w, av1.x, av1.y, av1.z, av1.w};
        float brr[4] = {bv.x, bv.y, bv.z, bv.w};
#pragma unroll
        for (int i = 0; i < 8; i++)
#pragma unroll
            for (int j = 0; j < 4; j++)
                acc[i][j] = fmaf(arr[i], brr[j], acc[i][j]);
    }

    float cb[4], sb[4];
#pragma unroll
    for (int j = 0; j < 4; j++) {
        int col = c0 + tx * 4 + j;
        if (MODE == 0) { cb[j] = bm[col] + be1[col]; sb[j] = bs[col]; }
        else           { cb[j] = 0.0f;               sb[j] = d_blr[col]; }
    }
#pragma unroll
    for (int i = 0; i < 8; i++) {
        int row = r0 + ty * 8 + i;
        if (row < NN) {
            float dg = (MODE == 0) ? d_deg[row] : 0.0f;
            float v0 = acc[i][0] + dg * cb[0] + sb[0];
            float v1 = acc[i][1] + dg * cb[1] + sb[1];
            float v2 = acc[i][2] + dg * cb[2] + sb[2];
            float v3 = acc[i][3] + dg * cb[3] + sb[3];
            float4 o;
            if (MODE == 0) o = make_float4(gelu_t(v0), gelu_t(v1), gelu_t(v2), gelu_t(v3));
            else           o = make_float4(v0, v1, v2, v3);
            *(float4*)(&C[(size_t)row * 256 + c0 + tx * 4]) = o;
        }
    }
}

// ------- fused GATv2 attention + pool, ONLINE softmax (warp per node) -----
__global__ void __launch_bounds__(256)
k_att(const float* __restrict__ ea, const float* __restrict__ We2,
      const float* __restrict__ att, const float* __restrict__ bias2) {
    __shared__ float sW[FE * OD];
    __shared__ float sA[OD];
    for (int i = threadIdx.x; i < FE * OD; i += 256) sW[i] = We2[i];
    for (int i = threadIdx.x; i < OD; i += 256) sA[i] = att[i];
    __syncthreads();

    int w = (blockIdx.x * blockDim.x + threadIdx.x) >> 5;
    if (w >= NN) return;
    int lane = threadIdx.x & 31;
    int k0 = lane * 4;
    int b = d_rowptr[w], e = d_rowptr[w + 1];
    float degf = (float)(e - b);
    float inv_deg = 1.0f / fmaxf(degf, 1.0f);

    float4 vr  = *(const float4*)(d_xlr + (size_t)w * 256 + 128 + k0);
    float4 sAv = *(const float4*)(&sA[k0]);

    float amax = -1e30f;
    float denom = 0.0f;
    float4 out = make_float4(0.f, 0.f, 0.f, 0.f);

    // single pass: alpha + online softmax + weighted accumulation
    for (int i = b; i <= e; i++) {
        int s;
        float ear[FE];
        if (i < e) {
            s = d_csrc[i];
            int eid = d_ceid[i];
            const float4* p4 = (const float4*)(ea + (size_t)eid * FE);
#pragma unroll
            for (int q = 0; q < 4; q++) {
                float4 ev = __ldg(p4 + q);
                ear[q * 4 + 0] = ev.x; ear[q * 4 + 1] = ev.y;
                ear[q * 4 + 2] = ev.z; ear[q * 4 + 3] = ev.w;
            }
        } else {
            s = w;
            const float4* p4 = (const float4*)(d_easum + (size_t)w * FE);
#pragma unroll
            for (int q = 0; q < 4; q++) {
                float4 ev = p4[q];
                ear[q * 4 + 0] = ev.x * inv_deg; ear[q * 4 + 1] = ev.y * inv_deg;
                ear[q * 4 + 2] = ev.z * inv_deg; ear[q * 4 + 3] = ev.w * inv_deg;
            }
        }
        float4 xl = *(const float4*)(d_xlr + (size_t)s * 256 + k0);
        float m0 = xl.x + vr.x, m1 = xl.y + vr.y, m2 = xl.z + vr.z, m3 = xl.w + vr.w;
#pragma unroll
        for (int q = 0; q < FE; q++) {
            float ev = ear[q];
            float4 wv = *(const float4*)(&sW[q * OD + k0]);
            m0 = fmaf(ev, wv.x, m0); m1 = fmaf(ev, wv.y, m1);
            m2 = fmaf(ev, wv.z, m2); m3 = fmaf(ev, wv.w, m3);
        }
        m0 = m0 > 0.f ? m0 : 0.2f * m0;
        m1 = m1 > 0.f ? m1 : 0.2f * m1;
        m2 = m2 > 0.f ? m2 : 0.2f * m2;
        m3 = m3 > 0.f ? m3 : 0.2f * m3;
        float a = m0 * sAv.x + m1 * sAv.y + m2 * sAv.z + m3 * sAv.w;
#pragma unroll
        for (int o = 16; o; o >>= 1) a += __shfl_xor_sync(0xFFFFFFFFu, a, o);

        float ev;
        if (a > amax) {              // warp-uniform branch (a identical on all lanes)
            float c = __expf(amax - a);
            denom *= c;
            out.x *= c; out.y *= c; out.z *= c; out.w *= c;
            amax = a;
            ev = 1.0f;
        } else {
            ev = __expf(a - amax);
        }
        denom += ev;
        out.x = fmaf(ev, xl.x, out.x); out.y = fmaf(ev, xl.y, out.y);
        out.z = fmaf(ev, xl.z, out.z); out.w = fmaf(ev, xl.w, out.w);
    }

    float invd = 1.0f / denom;
    float4 bb = *(const float4*)(bias2 + k0);
    out.x = fmaf(out.x, invd, bb.x); out.y = fmaf(out.y, invd, bb.y);
    out.z = fmaf(out.z, invd, bb.z); out.w = fmaf(out.w, invd, bb.w);

    int g = d_bat[w];
    atomicAdd((float4*)(d_gsum + (size_t)g * OD) + lane, out);
    if (lane == 0) atomicAdd(&d_gcnt[g], 1.0f);
}

// ---------------- FFN head ----------------
__global__ void k_ffn(const float* __restrict__ W1, const float* __restrict__ b1,
                      const float* __restrict__ W2, const float* __restrict__ b2,
                      float* __restrict__ y) {
    __shared__ float g[OD];
    __shared__ float red[128];
    int b = blockIdx.x, t = threadIdx.x;
    float inv = 1.0f / fmaxf(d_gcnt[b], 1.0f);
    g[t] = d_gsum[b * OD + t] * inv;
    __syncthreads();
    float part = 0.0f;
#pragma unroll
    for (int q = 0; q < 4; q++) {
        int j = t + q * 128;
        float acc = b1[j];
        for (int k = 0; k < OD; k++) acc = fmaf(g[k], W1[k * 512 + j], acc);
        part = fmaf(gelu_t(acc), W2[j], part);
    }
    red[t] = part;
    __syncthreads();
    for (int o = 64; o; o >>= 1) {
        if (t < o) red[t] += red[t + o];
        __syncthreads();
    }
    if (t == 0) y[b] = red[0] + b2[0];
}

// ---------------- launch ----------------
extern "C" void kernel_launch(void* const* d_in, const int* in_sizes, int n_in,
                              void* d_out, int out_size) {
    (void)in_sizes; (void)n_in; (void)out_size;
    const float* x     = (const float*)d_in[0];
    const int*   ei    = (const int*)d_in[1];
    const float* ea    = (const float*)d_in[2];
    const int*   bat   = (const int*)d_in[3];
    const float* Wmsg  = (const float*)d_in[4];
    const float* bmsg  = (const float*)d_in[5];
    const float* We1   = (const float*)d_in[6];
    const float* be1   = (const float*)d_in[7];
    const float* Wself = (const float*)d_in[8];
    const float* bself = (const float*)d_in[9];
    const float* Wl    = (const float*)d_in[10];
    const float* bl    = (const float*)d_in[11];
    const float* Wr    = (const float*)d_in[12];
    const float* br    = (const float*)d_in[13];
    const float* We2   = (const float*)d_in[14];
    const float* att   = (const float*)d_in[15];
    const float* bias2 = (const float*)d_in[16];
    const float* W1    = (const float*)d_in[17];
    const float* b1    = (const float*)d_in[18];
    const float* W2    = (const float*)d_in[19];
    const float* b2    = (const float*)d_in[20];
    float* y = (float*)d_out;

    k_zero<<<512, 256>>>();
    k_detect<<<1, 1>>>(ei);
    k_convert<<<(NE + 255) / 256, 256>>>(ei, bat);
    k_scanA<<<NSCB, SCB>>>();
    k_scanB<<<1, 256>>>();
    k_scanC<<<NSCB, SCB>>>();
    k_scatcsr<<<(NE + 255) / 256, 256>>>();
    k_gather<<<NN / 8, 256>>>(x, ea);
    k_packw<<<64, 256>>>(Wmsg, Wself, We1, Wl, bl, Wr, br);
    dim3 gg((NN + 127) / 128, 4);
    k_gemm<0><<<gg, 256>>>(x, bmsg, be1, bself);
    k_gemm<1><<<gg, 256>>>(x, nullptr, nullptr, nullptr);
    k_att<<<NN / 8, 256>>>(ea, We2, att, bias2);
    k_ffn<<<NG, 128>>>(W1, b1, W2, b2, y);
}